// round 6
// baseline (speedup 1.0000x reference)
#include <cuda_runtime.h>
#include <cuda_bf16.h>

// Problem constants
#define B_   2
#define S_   2048
#define D_   1024
#define H_   16
#define P_   2048
#define T_   4096
#define D3_  3072
#define OUT_OFF (B_*S_*D_)

// ---------------------------------------------------------------------------
// Scratch (device globals)
// ---------------------------------------------------------------------------
__device__ float g_qkv[(size_t)B_ * S_ * D3_];
__device__ __nv_bfloat16 g_xh [(size_t)B_ * S_ * D_];
__device__ __nv_bfloat16 g_xl [(size_t)B_ * S_ * D_];
__device__ __nv_bfloat16 g_ch [(size_t)B_ * S_ * D_];
__device__ __nv_bfloat16 g_cl [(size_t)B_ * S_ * D_];
__device__ __nv_bfloat16 g_kvh[(size_t)B_ * 2 * H_ * T_ * 64];
__device__ __nv_bfloat16 g_kvl[(size_t)B_ * 2 * H_ * T_ * 64];
__device__ __nv_bfloat16 g_wah[(size_t)D3_ * D_];
__device__ __nv_bfloat16 g_wal[(size_t)D3_ * D_];
__device__ __nv_bfloat16 g_wph[(size_t)D_ * D_];
__device__ __nv_bfloat16 g_wpl[(size_t)D_ * D_];

// ---------------------------------------------------------------------------
// Primitives
// ---------------------------------------------------------------------------
__device__ __forceinline__ void mma_bf16(float* d, const unsigned* a, const unsigned* b) {
    asm volatile(
        "mma.sync.aligned.m16n8k16.row.col.f32.bf16.bf16.f32 "
        "{%0,%1,%2,%3}, {%4,%5,%6,%7}, {%8,%9}, {%0,%1,%2,%3};\n"
        : "+f"(d[0]), "+f"(d[1]), "+f"(d[2]), "+f"(d[3])
        : "r"(a[0]), "r"(a[1]), "r"(a[2]), "r"(a[3]), "r"(b[0]), "r"(b[1]));
}
__device__ __forceinline__ void ldsm_x4(unsigned* r, unsigned addr) {
    asm volatile("ldmatrix.sync.aligned.m8n8.x4.shared.b16 {%0,%1,%2,%3}, [%4];"
        : "=r"(r[0]), "=r"(r[1]), "=r"(r[2]), "=r"(r[3]) : "r"(addr));
}
__device__ __forceinline__ void ldsm_x4_t(unsigned* r, unsigned addr) {
    asm volatile("ldmatrix.sync.aligned.m8n8.x4.trans.shared.b16 {%0,%1,%2,%3}, [%4];"
        : "=r"(r[0]), "=r"(r[1]), "=r"(r[2]), "=r"(r[3]) : "r"(addr));
}
__device__ __forceinline__ void split2(float x, float y, unsigned& hi, unsigned& lo) {
    __nv_bfloat162 h = __floats2bfloat162_rn(x, y);
    float rx = x - __bfloat162float(h.x);
    float ry = y - __bfloat162float(h.y);
    __nv_bfloat162 l = __floats2bfloat162_rn(rx, ry);
    hi = *(unsigned*)&h;
    lo = *(unsigned*)&l;
}
__device__ __forceinline__ unsigned saddr(const void* p) {
    return (unsigned)__cvta_generic_to_shared(p);
}
__device__ __forceinline__ void cp16(unsigned dst, const void* src) {
    asm volatile("cp.async.cg.shared.global [%0], [%1], 16;\n" :: "r"(dst), "l"(src));
}
__device__ __forceinline__ void cp_commit() {
    asm volatile("cp.async.commit_group;\n");
}
template<int N> __device__ __forceinline__ void cp_wait() {
    asm volatile("cp.async.wait_group %0;\n" :: "n"(N));
}

// ---------------------------------------------------------------------------
// Split x -> bf16 hi/lo
// ---------------------------------------------------------------------------
__global__ void split_x(const float4* __restrict__ x4,
                        __nv_bfloat16* __restrict__ xh,
                        __nv_bfloat16* __restrict__ xl)
{
    int i = blockIdx.x * blockDim.x + threadIdx.x;
    float4 v = x4[i];
    unsigned h01, l01, h23, l23;
    split2(v.x, v.y, h01, l01);
    split2(v.z, v.w, h23, l23);
    *(uint2*)&xh[(size_t)i * 4] = make_uint2(h01, h23);
    *(uint2*)&xl[(size_t)i * 4] = make_uint2(l01, l23);
}

// ---------------------------------------------------------------------------
// Weight split+transpose: w[K][N] f32 -> wt_hi/lo [N][K] bf16
// ---------------------------------------------------------------------------
__global__ __launch_bounds__(256) void split_w(
    const float* __restrict__ w, __nv_bfloat16* __restrict__ th,
    __nv_bfloat16* __restrict__ tl, int K, int N)
{
    __shared__ float t[32][33];
    const int k0 = blockIdx.x << 5, n0 = blockIdx.y << 5;
    const int c = threadIdx.x & 31, r8 = threadIdx.x >> 5;
#pragma unroll
    for (int i = 0; i < 4; i++) {
        int k = r8 + (i << 3);
        t[k][c] = w[(size_t)(k0 + k) * N + n0 + c];
    }
    __syncthreads();
#pragma unroll
    for (int i = 0; i < 4; i++) {
        int n = r8 + (i << 3);
        float v = t[c][n];
        __nv_bfloat16 h = __float2bfloat16(v);
        th[(size_t)(n0 + n) * K + k0 + c] = h;
        tl[(size_t)(n0 + n) * K + k0 + c] = __float2bfloat16(v - __bfloat162float(h));
    }
}

// ---------------------------------------------------------------------------
// Build `present` f32 + split K/V bf16 hi/lo
// ---------------------------------------------------------------------------
__global__ void build_present(const float4* __restrict__ past4,
                              const float4* __restrict__ qkv4,
                              float4* __restrict__ pres4,
                              __nv_bfloat16* __restrict__ kvh,
                              __nv_bfloat16* __restrict__ kvl)
{
    int i = blockIdx.x * blockDim.x + threadIdx.x;
    int d4  = i & 15;
    int j   = i >> 4;
    int p   = j & (T_ - 1);
    int chh = j >> 12;
    int h = chh & (H_ - 1);
    int c = (chh >> 4) & 1;
    int b = chh >> 5;

    float4 v;
    if (p < P_) {
        v = past4[(((size_t)((b * 2 + c) * H_ + h) * P_ + p) << 4) + d4];
    } else {
        int s = p - P_;
        v = qkv4[(size_t)(b * S_ + s) * 768 + (c + 1) * 256 + h * 16 + d4];
    }
    pres4[i] = v;
    unsigned h01, l01, h23, l23;
    split2(v.x, v.y, h01, l01);
    split2(v.z, v.w, h23, l23);
    *(uint2*)&kvh[(size_t)i * 4] = make_uint2(h01, h23);
    *(uint2*)&kvl[(size_t)i * 4] = make_uint2(l01, l23);
}

// ---------------------------------------------------------------------------
// GEMM, pre-split operands, cp.async 2-stage (unchanged from R5).
// ---------------------------------------------------------------------------
__global__ __launch_bounds__(256, 2) void gemm_presplit(
    const __nv_bfloat16* __restrict__ Ah, const __nv_bfloat16* __restrict__ Al,
    const __nv_bfloat16* __restrict__ Wh, const __nv_bfloat16* __restrict__ Wl,
    const float* __restrict__ bias, float* __restrict__ C,
    int M, int N, int K)
{
    extern __shared__ char sg[];
    const unsigned sb = saddr(sg);

    const int tid  = threadIdx.x;
    const int lane = tid & 31;
    const int warp = tid >> 5;
    const int g = lane >> 2, t = lane & 3;
    const int mi = lane >> 3, rr = lane & 7;
    const int aro = ((mi & 1) << 3) + rr, aco = (mi >> 1) << 3;
    const int bno = ((mi >> 1) << 3) + rr, bko = (mi & 1) << 3;
    const int wm = warp >> 2, wn = warp & 3;
    const int bm = blockIdx.y << 7, bn = blockIdx.x << 7;

    auto issue = [&](int k0, int st) {
        unsigned b0 = sb + st * 40960;
#pragma unroll
        for (int p = 0; p < 2; p++) {
            int idx = tid + (p << 8);
            int r = idx >> 2, cb = (idx & 3) << 4;
            size_t ga = ((size_t)(bm + r) * K + k0) * 2 + cb;
            size_t gb = ((size_t)(bn + r) * K + k0) * 2 + cb;
            unsigned d = b0 + r * 80 + cb;
            cp16(d,         (const char*)Ah + ga);
            cp16(d + 10240, (const char*)Al + ga);
            cp16(d + 20480, (const char*)Wh + gb);
            cp16(d + 30720, (const char*)Wl + gb);
        }
    };

    float acc[4][4][4];
#pragma unroll
    for (int i = 0; i < 4; i++)
#pragma unroll
        for (int j = 0; j < 4; j++)
#pragma unroll
            for (int r = 0; r < 4; r++) acc[i][j][r] = 0.f;

    const int nK = K >> 5;
    issue(0, 0);
    cp_commit();

    for (int it = 0; it < nK; it++) {
        if (it + 1 < nK) { issue((it + 1) << 5, (it + 1) & 1); cp_commit(); cp_wait<1>(); }
        else             { cp_wait<0>(); }
        __syncthreads();

        unsigned b0 = sb + (it & 1) * 40960;
#pragma unroll
        for (int kc = 0; kc < 2; kc++) {
            unsigned ah[4][4], al[4][4];
#pragma unroll
            for (int mt = 0; mt < 4; mt++) {
                unsigned off = b0 + (unsigned)((((wm << 6) + (mt << 4) + aro) * 40 + (kc << 4) + aco) * 2);
                ldsm_x4(ah[mt], off);
                ldsm_x4(al[mt], off + 10240);
            }
#pragma unroll
            for (int ntp = 0; ntp < 2; ntp++) {
                unsigned bh[4], bl[4];
                unsigned off = b0 + 20480 + (unsigned)((((wn << 5) + (ntp << 4) + bno) * 40 + (kc << 4) + bko) * 2);
                ldsm_x4(bh, off);
                ldsm_x4(bl, off + 10240);
#pragma unroll
                for (int hf = 0; hf < 2; hf++) {
                    int nt = (ntp << 1) + hf;
#pragma unroll
                    for (int mt = 0; mt < 4; mt++) mma_bf16(acc[mt][nt], ah[mt], bh + 2*hf);
#pragma unroll
                    for (int mt = 0; mt < 4; mt++) mma_bf16(acc[mt][nt], ah[mt], bl + 2*hf);
#pragma unroll
                    for (int mt = 0; mt < 4; mt++) mma_bf16(acc[mt][nt], al[mt], bh + 2*hf);
                }
            }
        }
        __syncthreads();
    }

#pragma unroll
    for (int mt = 0; mt < 4; mt++) {
#pragma unroll
        for (int nt = 0; nt < 4; nt++) {
            int row = bm + (wm << 6) + (mt << 4) + g;
            int col = bn + (wn << 5) + (nt << 3) + 2 * t;
            float bx = bias[col], by = bias[col + 1];
            *(float2*)&C[(size_t)row * N + col] =
                make_float2(acc[mt][nt][0] + bx, acc[mt][nt][1] + by);
            *(float2*)&C[(size_t)(row + 8) * N + col] =
                make_float2(acc[mt][nt][2] + bx, acc[mt][nt][3] + by);
        }
    }
}

// ---------------------------------------------------------------------------
// Flash attention BQ=128: 256 threads (8 warps x 16 rows), BK=64.
// KV 2-stage cp.async (36864 B/stage); Q hi/lo in dedicated smem region
// (re-ldmatrix'ed per iteration -> low reg pressure, 2 blocks/SM).
// smem layout (bytes):
//   stage st (st=0,1): base st*36864:  Kh +0, Kl +9216, Vh +18432, Vl +27648
//   Q: hi at 73728, lo at 92160 (128 rows x 144 B)
//   total 110592
// Scores computed in log2 domain (Q pre-scaled by log2(e)/8, exp2f).
// ---------------------------------------------------------------------------
__global__ __launch_bounds__(256, 2) void flash_bq128(
    const float* __restrict__ qkv,
    const __nv_bfloat16* __restrict__ kvh, const __nv_bfloat16* __restrict__ kvl,
    __nv_bfloat16* __restrict__ ctxh, __nv_bfloat16* __restrict__ ctxl)
{
    extern __shared__ char sf[];
    const unsigned sb = saddr(sf);

    const int tid  = threadIdx.x;
    const int lane = tid & 31;
    const int w    = tid >> 5;          // warp 0..7 -> rows 16w..16w+15
    const int g = lane >> 2, t = lane & 3;
    const int mi = lane >> 3, rr = lane & 7;
    const int aro = ((mi & 1) << 3) + rr, aco = (mi >> 1) << 3;  // A frag (Q, P)
    const int kno = ((mi >> 1) << 3) + rr, kko = (mi & 1) << 3;  // B frag (K)
    const int vro = ((mi & 1) << 3) + rr, vco = (mi >> 1) << 3;  // B frag (V, trans)
    const int r0 = (w << 4) + g, r1 = r0 + 8;

    const int bh = blockIdx.y;
    const int b = bh >> 4, h = bh & 15;
    const int qt = gridDim.x - 1 - blockIdx.x;   // big tiles first
    const int q0 = qt << 7;

    const float* Qg = qkv + (size_t)(b * S_ + q0) * D3_ + h * 64;
    const __nv_bfloat16* Kgh = kvh + ((size_t)(b * 2    ) * H_ + h) * T_ * 64;
    const __nv_bfloat16* Kgl = kvl + ((size_t)(b * 2    ) * H_ + h) * T_ * 64;
    const __nv_bfloat16* Vgh = kvh + ((size_t)(b * 2 + 1) * H_ + h) * T_ * 64;
    const __nv_bfloat16* Vgl = kvl + ((size_t)(b * 2 + 1) * H_ + h) * T_ * 64;

    __nv_bfloat16* sQh = (__nv_bfloat16*)(sf + 73728);
    __nv_bfloat16* sQl = (__nv_bfloat16*)(sf + 92160);
    const unsigned sqa = sb + 73728;

    // ---- Q: load f32, scale by log2(e)/8, split ----
    const float QSCALE = 0.125f * 1.4426950408889634f;
#pragma unroll
    for (int p = 0; p < 8; p++) {
        int idx = tid + (p << 8);          // 2048 float4 = 128 rows x 16
        int r = idx >> 4, c4 = (idx & 15) << 2;
        float4 v = *(const float4*)&Qg[(size_t)r * D3_ + c4];
        v.x *= QSCALE; v.y *= QSCALE; v.z *= QSCALE; v.w *= QSCALE;
        unsigned h01, l01, h23, l23;
        split2(v.x, v.y, h01, l01);
        split2(v.z, v.w, h23, l23);
        *(uint2*)&sQh[r * 72 + c4] = make_uint2(h01, h23);
        *(uint2*)&sQl[r * 72 + c4] = make_uint2(l01, l23);
    }

    auto issueKV = [&](int k0, int st) {
        unsigned b0 = sb + st * 36864;
        size_t gr = (size_t)k0 * 128;      // byte offset of row k0
#pragma unroll
        for (int p = 0; p < 2; p++) {
            int idx = tid + (p << 8);      // 512 chunks of 16B per tile
            int r = idx >> 3, cb = (idx & 7) << 4;
            unsigned d = b0 + r * 144 + cb;
            size_t go = gr + (size_t)r * 128 + cb;
            cp16(d,         (const char*)Kgh + go);
            cp16(d +  9216, (const char*)Kgl + go);
            cp16(d + 18432, (const char*)Vgh + go);
            cp16(d + 27648, (const char*)Vgl + go);
        }
    };

    float m0 = -1e30f, m1 = -1e30f, l0 = 0.f, l1 = 0.f;
    float o[8][4];
#pragma unroll
    for (int nt = 0; nt < 8; nt++)
#pragma unroll
        for (int r = 0; r < 4; r++) o[nt][r] = 0.f;

    __syncthreads();        // Q smem ready (it is never overwritten)
    const int nIter = (P_ >> 6) + (q0 >> 6) + 2;
    issueKV(0, 0);
    cp_commit();

    for (int it = 0; it < nIter; it++) {
        if (it + 1 < nIter) { issueKV((it + 1) << 6, (it + 1) & 1); cp_commit(); cp_wait<1>(); }
        else                { cp_wait<0>(); }
        __syncthreads();

        // last iteration: warps 0-3 (rows<64) are fully masked -> skip compute
        if (it + 1 < nIter || w >= 4) {
            unsigned kb = sb + (it & 1) * 36864;

            // ---- S = Q K^T ----
            float s[8][4];
#pragma unroll
            for (int nt = 0; nt < 8; nt++)
#pragma unroll
                for (int r = 0; r < 4; r++) s[nt][r] = 0.f;

#pragma unroll
            for (int kc = 0; kc < 4; kc++) {
                unsigned qh[4], ql[4];
                unsigned qoff = sqa + (unsigned)((((w << 4) + aro) * 72 + (kc << 4) + aco) * 2);
                ldsm_x4(qh, qoff);
                ldsm_x4(ql, qoff + 18432);
#pragma unroll
                for (int ntp = 0; ntp < 4; ntp++) {
                    unsigned bhh[4], bll[4];
                    unsigned off = kb + (unsigned)((((ntp << 4) + kno) * 72 + (kc << 4) + kko) * 2);
                    ldsm_x4(bhh, off);
                    ldsm_x4(bll, off + 9216);
                    int nt = ntp << 1;
                    mma_bf16(s[nt],     qh, bhh);
                    mma_bf16(s[nt + 1], qh, bhh + 2);
                    mma_bf16(s[nt],     qh, bll);
                    mma_bf16(s[nt + 1], qh, bll + 2);
                    mma_bf16(s[nt],     ql, bhh);
                    mma_bf16(s[nt + 1], ql, bhh + 2);
                }
            }

            // ---- causal mask (last two iterations only) ----
            const int kRel = (it << 6) - P_ - q0;   // key_global - row_global offset
            if (kRel + 63 > 0) {
#pragma unroll
                for (int nt = 0; nt < 8; nt++) {
                    int c0 = (nt << 3) + 2 * t + kRel;
                    if (c0     > r0) s[nt][0] = -1e30f;
                    if (c0 + 1 > r0) s[nt][1] = -1e30f;
                    if (c0     > r1) s[nt][2] = -1e30f;
                    if (c0 + 1 > r1) s[nt][3] = -1e30f;
                }
            }

            // ---- online softmax (log2 domain) ----
            float mx0 = -1e30f, mx1 = -1e30f;
#pragma unroll
            for (int nt = 0; nt < 8; nt++) {
                mx0 = fmaxf(mx0, fmaxf(s[nt][0], s[nt][1]));
                mx1 = fmaxf(mx1, fmaxf(s[nt][2], s[nt][3]));
            }
            mx0 = fmaxf(mx0, __shfl_xor_sync(0xffffffffu, mx0, 1));
            mx0 = fmaxf(mx0, __shfl_xor_sync(0xffffffffu, mx0, 2));
            mx1 = fmaxf(mx1, __shfl_xor_sync(0xffffffffu, mx1, 1));
            mx1 = fmaxf(mx1, __shfl_xor_sync(0xffffffffu, mx1, 2));
            float nm0 = fmaxf(m0, mx0), nm1 = fmaxf(m1, mx1);
            float sc0 = exp2f(m0 - nm0), sc1 = exp2f(m1 - nm1);
            float rs0 = 0.f, rs1 = 0.f;
#pragma unroll
            for (int nt = 0; nt < 8; nt++) {
                s[nt][0] = exp2f(s[nt][0] - nm0); rs0 += s[nt][0];
                s[nt][1] = exp2f(s[nt][1] - nm0); rs0 += s[nt][1];
                s[nt][2] = exp2f(s[nt][2] - nm1); rs1 += s[nt][2];
                s[nt][3] = exp2f(s[nt][3] - nm1); rs1 += s[nt][3];
            }
            rs0 += __shfl_xor_sync(0xffffffffu, rs0, 1);
            rs0 += __shfl_xor_sync(0xffffffffu, rs0, 2);
            rs1 += __shfl_xor_sync(0xffffffffu, rs1, 1);
            rs1 += __shfl_xor_sync(0xffffffffu, rs1, 2);
            l0 = l0 * sc0 + rs0;  m0 = nm0;
            l1 = l1 * sc1 + rs1;  m1 = nm1;
#pragma unroll
            for (int nt = 0; nt < 8; nt++) {
                o[nt][0] *= sc0; o[nt][1] *= sc0;
                o[nt][2] *= sc1; o[nt][3] *= sc1;
            }

            // ---- O += P V ----
#pragma unroll
            for (int kc = 0; kc < 4; kc++) {
                unsigned ah[4], al[4];
                split2(s[2*kc    ][0], s[2*kc    ][1], ah[0], al[0]);
                split2(s[2*kc    ][2], s[2*kc    ][3], ah[1], al[1]);
                split2(s[2*kc + 1][0], s[2*kc + 1][1], ah[2], al[2]);
                split2(s[2*kc + 1][2], s[2*kc + 1][3], ah[3], al[3]);
#pragma unroll
                for (int ntp = 0; ntp < 4; ntp++) {
                    unsigned vh[4], vl[4];
                    unsigned off = kb + 18432 + (unsigned)((((kc << 4) + vro) * 72 + (ntp << 4) + vco) * 2);
                    ldsm_x4_t(vh, off);
                    ldsm_x4_t(vl, off + 9216);
                    int nt = ntp << 1;
                    mma_bf16(o[nt],     ah, vh);
                    mma_bf16(o[nt + 1], ah, vh + 2);
                    mma_bf16(o[nt],     ah, vl);
                    mma_bf16(o[nt + 1], ah, vl + 2);
                    mma_bf16(o[nt],     al, vh);
                    mma_bf16(o[nt + 1], al, vh + 2);
                }
            }
        }
        __syncthreads();
    }

    // epilogue: normalize + split-write ctx hi/lo
    float inv0 = 1.f / l0, inv1 = 1.f / l1;
    size_t o0 = (size_t)(b * S_ + q0 + r0) * D_ + h * 64;
    size_t o1 = (size_t)(b * S_ + q0 + r1) * D_ + h * 64;
#pragma unroll
    for (int nt = 0; nt < 8; nt++) {
        int c0 = (nt << 3) + 2 * t;
        unsigned hh, ll;
        split2(o[nt][0] * inv0, o[nt][1] * inv0, hh, ll);
        *(unsigned*)&ctxh[o0 + c0] = hh;
        *(unsigned*)&ctxl[o0 + c0] = ll;
        split2(o[nt][2] * inv1, o[nt][3] * inv1, hh, ll);
        *(unsigned*)&ctxh[o1 + c0] = hh;
        *(unsigned*)&ctxl[o1 + c0] = ll;
    }
}

// ---------------------------------------------------------------------------
// Launch
// ---------------------------------------------------------------------------
extern "C" void kernel_launch(void* const* d_in, const int* in_sizes, int n_in,
                              void* d_out, int out_size)
{
    const float* x      = (const float*)d_in[0];
    // d_in[1] = mask: exactly causal -> applied analytically
    const float* past   = (const float*)d_in[2];
    const float* w_attn = (const float*)d_in[3];
    const float* b_attn = (const float*)d_in[4];
    const float* w_proj = (const float*)d_in[5];
    const float* b_proj = (const float*)d_in[6];

    float* out     = (float*)d_out;
    float* present = out + OUT_OFF;

    void* p;
    float* qkv;
    __nv_bfloat16 *xh, *xl, *ch, *cl, *kvh, *kvl, *wah, *wal, *wph, *wpl;
    cudaGetSymbolAddress(&p, g_qkv); qkv = (float*)p;
    cudaGetSymbolAddress(&p, g_xh);  xh  = (__nv_bfloat16*)p;
    cudaGetSymbolAddress(&p, g_xl);  xl  = (__nv_bfloat16*)p;
    cudaGetSymbolAddress(&p, g_ch);  ch  = (__nv_bfloat16*)p;
    cudaGetSymbolAddress(&p, g_cl);  cl  = (__nv_bfloat16*)p;
    cudaGetSymbolAddress(&p, g_kvh); kvh = (__nv_bfloat16*)p;
    cudaGetSymbolAddress(&p, g_kvl); kvl = (__nv_bfloat16*)p;
    cudaGetSymbolAddress(&p, g_wah); wah = (__nv_bfloat16*)p;
    cudaGetSymbolAddress(&p, g_wal); wal = (__nv_bfloat16*)p;
    cudaGetSymbolAddress(&p, g_wph); wph = (__nv_bfloat16*)p;
    cudaGetSymbolAddress(&p, g_wpl); wpl = (__nv_bfloat16*)p;

    const int GEMM_SMEM  = 2 * 40960;          // 81920
    const int FLASH_SMEM = 2 * 36864 + 36864;  // 110592
    cudaFuncSetAttribute(gemm_presplit,
                         cudaFuncAttributeMaxDynamicSharedMemorySize, GEMM_SMEM);
    cudaFuncSetAttribute(flash_bq128,
                         cudaFuncAttributeMaxDynamicSharedMemorySize, FLASH_SMEM);

    // 0. pre-split inputs/weights
    split_x<<<(B_ * S_ * D_ / 4) / 256, 256>>>((const float4*)x, xh, xl);
    split_w<<<dim3(D_ / 32, D3_ / 32), 256>>>(w_attn, wah, wal, D_, D3_);
    split_w<<<dim3(D_ / 32, D_  / 32), 256>>>(w_proj, wph, wpl, D_, D_);

    // 1. QKV projection
    gemm_presplit<<<dim3(D3_ / 128, (B_ * S_) / 128), 256, GEMM_SMEM>>>(
        xh, xl, wah, wal, b_attn, qkv, B_ * S_, D3_, D_);

    // 2. present (f32, into d_out) + K/V hi/lo split
    build_present<<<(B_ * 2 * H_ * T_ * 16) / 256, 256>>>(
        (const float4*)past, (const float4*)qkv, (float4*)present, kvh, kvl);

    // 3. flash attention -> ctx hi/lo
    flash_bq128<<<dim3(S_ / 128, B_ * H_), 256, FLASH_SMEM>>>(
        qkv, kvh, kvl, ch, cl);

    // 4. output projection
    gemm_presplit<<<dim3(D_ / 128, (B_ * S_) / 128), 256, GEMM_SMEM>>>(
        ch, cl, wph, wpl, b_proj, out, B_ * S_, D_, D_);
}

// round 8
// speedup vs baseline: 1.0136x; 1.0136x over previous
#include <cuda_runtime.h>
#include <cuda_bf16.h>

// Problem constants
#define B_   2
#define S_   2048
#define D_   1024
#define H_   16
#define P_   2048
#define T_   4096
#define D3_  3072
#define OUT_OFF (B_*S_*D_)

// ---------------------------------------------------------------------------
// Scratch (device globals)
// ---------------------------------------------------------------------------
__device__ float g_qkv[(size_t)B_ * S_ * D3_];
__device__ __nv_bfloat16 g_xh [(size_t)B_ * S_ * D_];
__device__ __nv_bfloat16 g_xl [(size_t)B_ * S_ * D_];
__device__ __nv_bfloat16 g_ch [(size_t)B_ * S_ * D_];
__device__ __nv_bfloat16 g_cl [(size_t)B_ * S_ * D_];
__device__ __nv_bfloat16 g_kvh[(size_t)B_ * 2 * H_ * T_ * 64];
__device__ __nv_bfloat16 g_kvl[(size_t)B_ * 2 * H_ * T_ * 64];
__device__ __nv_bfloat16 g_wah[(size_t)D3_ * D_];
__device__ __nv_bfloat16 g_wal[(size_t)D3_ * D_];
__device__ __nv_bfloat16 g_wph[(size_t)D_ * D_];
__device__ __nv_bfloat16 g_wpl[(size_t)D_ * D_];

// ---------------------------------------------------------------------------
// Primitives
// ---------------------------------------------------------------------------
__device__ __forceinline__ void mma_bf16(float* d, const unsigned* a, const unsigned* b) {
    asm volatile(
        "mma.sync.aligned.m16n8k16.row.col.f32.bf16.bf16.f32 "
        "{%0,%1,%2,%3}, {%4,%5,%6,%7}, {%8,%9}, {%0,%1,%2,%3};\n"
        : "+f"(d[0]), "+f"(d[1]), "+f"(d[2]), "+f"(d[3])
        : "r"(a[0]), "r"(a[1]), "r"(a[2]), "r"(a[3]), "r"(b[0]), "r"(b[1]));
}
__device__ __forceinline__ void ldsm_x4(unsigned* r, unsigned addr) {
    asm volatile("ldmatrix.sync.aligned.m8n8.x4.shared.b16 {%0,%1,%2,%3}, [%4];"
        : "=r"(r[0]), "=r"(r[1]), "=r"(r[2]), "=r"(r[3]) : "r"(addr));
}
__device__ __forceinline__ void ldsm_x4_t(unsigned* r, unsigned addr) {
    asm volatile("ldmatrix.sync.aligned.m8n8.x4.trans.shared.b16 {%0,%1,%2,%3}, [%4];"
        : "=r"(r[0]), "=r"(r[1]), "=r"(r[2]), "=r"(r[3]) : "r"(addr));
}
__device__ __forceinline__ void split2(float x, float y, unsigned& hi, unsigned& lo) {
    __nv_bfloat162 h = __floats2bfloat162_rn(x, y);
    float rx = x - __bfloat162float(h.x);
    float ry = y - __bfloat162float(h.y);
    __nv_bfloat162 l = __floats2bfloat162_rn(rx, ry);
    hi = *(unsigned*)&h;
    lo = *(unsigned*)&l;
}
__device__ __forceinline__ unsigned saddr(const void* p) {
    return (unsigned)__cvta_generic_to_shared(p);
}
__device__ __forceinline__ void cp16(unsigned dst, const void* src) {
    asm volatile("cp.async.cg.shared.global [%0], [%1], 16;\n" :: "r"(dst), "l"(src));
}
__device__ __forceinline__ void cp_commit() {
    asm volatile("cp.async.commit_group;\n");
}
template<int N> __device__ __forceinline__ void cp_wait() {
    asm volatile("cp.async.wait_group %0;\n" :: "n"(N));
}

// ---------------------------------------------------------------------------
// Split x -> bf16 hi/lo
// ---------------------------------------------------------------------------
__global__ void split_x(const float4* __restrict__ x4,
                        __nv_bfloat16* __restrict__ xh,
                        __nv_bfloat16* __restrict__ xl)
{
    int i = blockIdx.x * blockDim.x + threadIdx.x;
    float4 v = x4[i];
    unsigned h01, l01, h23, l23;
    split2(v.x, v.y, h01, l01);
    split2(v.z, v.w, h23, l23);
    *(uint2*)&xh[(size_t)i * 4] = make_uint2(h01, h23);
    *(uint2*)&xl[(size_t)i * 4] = make_uint2(l01, l23);
}

// ---------------------------------------------------------------------------
// Weight split+transpose: w[K][N] f32 -> wt_hi/lo [N][K] bf16
// ---------------------------------------------------------------------------
__global__ __launch_bounds__(256) void split_w(
    const float* __restrict__ w, __nv_bfloat16* __restrict__ th,
    __nv_bfloat16* __restrict__ tl, int K, int N)
{
    __shared__ float t[32][33];
    const int k0 = blockIdx.x << 5, n0 = blockIdx.y << 5;
    const int c = threadIdx.x & 31, r8 = threadIdx.x >> 5;
#pragma unroll
    for (int i = 0; i < 4; i++) {
        int k = r8 + (i << 3);
        t[k][c] = w[(size_t)(k0 + k) * N + n0 + c];
    }
    __syncthreads();
#pragma unroll
    for (int i = 0; i < 4; i++) {
        int n = r8 + (i << 3);
        float v = t[c][n];
        __nv_bfloat16 h = __float2bfloat16(v);
        th[(size_t)(n0 + n) * K + k0 + c] = h;
        tl[(size_t)(n0 + n) * K + k0 + c] = __float2bfloat16(v - __bfloat162float(h));
    }
}

// ---------------------------------------------------------------------------
// Build `present` f32 + split K/V bf16 hi/lo
// ---------------------------------------------------------------------------
__global__ void build_present(const float4* __restrict__ past4,
                              const float4* __restrict__ qkv4,
                              float4* __restrict__ pres4,
                              __nv_bfloat16* __restrict__ kvh,
                              __nv_bfloat16* __restrict__ kvl)
{
    int i = blockIdx.x * blockDim.x + threadIdx.x;
    int d4  = i & 15;
    int j   = i >> 4;
    int p   = j & (T_ - 1);
    int chh = j >> 12;
    int h = chh & (H_ - 1);
    int c = (chh >> 4) & 1;
    int b = chh >> 5;

    float4 v;
    if (p < P_) {
        v = past4[(((size_t)((b * 2 + c) * H_ + h) * P_ + p) << 4) + d4];
    } else {
        int s = p - P_;
        v = qkv4[(size_t)(b * S_ + s) * 768 + (c + 1) * 256 + h * 16 + d4];
    }
    pres4[i] = v;
    unsigned h01, l01, h23, l23;
    split2(v.x, v.y, h01, l01);
    split2(v.z, v.w, h23, l23);
    *(uint2*)&kvh[(size_t)i * 4] = make_uint2(h01, h23);
    *(uint2*)&kvl[(size_t)i * 4] = make_uint2(l01, l23);
}

// ---------------------------------------------------------------------------
// GEMM, pre-split operands, cp.async 2-stage, term-major mma order
// (same-accumulator reuse distance 8; per-acc summation order unchanged).
// ---------------------------------------------------------------------------
__global__ __launch_bounds__(256, 2) void gemm_presplit(
    const __nv_bfloat16* __restrict__ Ah, const __nv_bfloat16* __restrict__ Al,
    const __nv_bfloat16* __restrict__ Wh, const __nv_bfloat16* __restrict__ Wl,
    const float* __restrict__ bias, float* __restrict__ C,
    int M, int N, int K)
{
    extern __shared__ char sg[];
    const unsigned sb = saddr(sg);

    const int tid  = threadIdx.x;
    const int lane = tid & 31;
    const int warp = tid >> 5;
    const int g = lane >> 2, t = lane & 3;
    const int mi = lane >> 3, rr = lane & 7;
    const int aro = ((mi & 1) << 3) + rr, aco = (mi >> 1) << 3;
    const int bno = ((mi >> 1) << 3) + rr, bko = (mi & 1) << 3;
    const int wm = warp >> 2, wn = warp & 3;
    const int bm = blockIdx.y << 7, bn = blockIdx.x << 7;

    auto issue = [&](int k0, int st) {
        unsigned b0 = sb + st * 40960;
#pragma unroll
        for (int p = 0; p < 2; p++) {
            int idx = tid + (p << 8);
            int r = idx >> 2, cb = (idx & 3) << 4;
            size_t ga = ((size_t)(bm + r) * K + k0) * 2 + cb;
            size_t gb = ((size_t)(bn + r) * K + k0) * 2 + cb;
            unsigned d = b0 + r * 80 + cb;
            cp16(d,         (const char*)Ah + ga);
            cp16(d + 10240, (const char*)Al + ga);
            cp16(d + 20480, (const char*)Wh + gb);
            cp16(d + 30720, (const char*)Wl + gb);
        }
    };

    float acc[4][4][4];
#pragma unroll
    for (int i = 0; i < 4; i++)
#pragma unroll
        for (int j = 0; j < 4; j++)
#pragma unroll
            for (int r = 0; r < 4; r++) acc[i][j][r] = 0.f;

    const int nK = K >> 5;
    issue(0, 0);
    cp_commit();

    for (int it = 0; it < nK; it++) {
        if (it + 1 < nK) { issue((it + 1) << 5, (it + 1) & 1); cp_commit(); cp_wait<1>(); }
        else             { cp_wait<0>(); }
        __syncthreads();

        unsigned b0 = sb + (it & 1) * 40960;
#pragma unroll
        for (int kc = 0; kc < 2; kc++) {
            unsigned ah[4][4], al[4][4];
#pragma unroll
            for (int mt = 0; mt < 4; mt++) {
                unsigned off = b0 + (unsigned)((((wm << 6) + (mt << 4) + aro) * 40 + (kc << 4) + aco) * 2);
                ldsm_x4(ah[mt], off);
                ldsm_x4(al[mt], off + 10240);
            }
#pragma unroll
            for (int ntp = 0; ntp < 2; ntp++) {
                unsigned bh[4], bl[4];
                unsigned off = b0 + 20480 + (unsigned)((((wn << 5) + (ntp << 4) + bno) * 40 + (kc << 4) + bko) * 2);
                ldsm_x4(bh, off);
                ldsm_x4(bl, off + 10240);
                const int n0 = ntp << 1;
                // term 1 (hi*hi): 8 distinct accumulators
#pragma unroll
                for (int mt = 0; mt < 4; mt++) {
                    mma_bf16(acc[mt][n0],     ah[mt], bh);
                    mma_bf16(acc[mt][n0 + 1], ah[mt], bh + 2);
                }
                // term 2 (hi*lo)
#pragma unroll
                for (int mt = 0; mt < 4; mt++) {
                    mma_bf16(acc[mt][n0],     ah[mt], bl);
                    mma_bf16(acc[mt][n0 + 1], ah[mt], bl + 2);
                }
                // term 3 (lo*hi)
#pragma unroll
                for (int mt = 0; mt < 4; mt++) {
                    mma_bf16(acc[mt][n0],     al[mt], bh);
                    mma_bf16(acc[mt][n0 + 1], al[mt], bh + 2);
                }
            }
        }
        __syncthreads();
    }

#pragma unroll
    for (int mt = 0; mt < 4; mt++) {
#pragma unroll
        for (int nt = 0; nt < 4; nt++) {
            int row = bm + (wm << 6) + (mt << 4) + g;
            int col = bn + (wn << 5) + (nt << 3) + 2 * t;
            float bx = bias[col], by = bias[col + 1];
            *(float2*)&C[(size_t)row * N + col] =
                make_float2(acc[mt][nt][0] + bx, acc[mt][nt][1] + by);
            *(float2*)&C[(size_t)(row + 8) * N + col] =
                make_float2(acc[mt][nt][2] + bx, acc[mt][nt][3] + by);
        }
    }
}

// ---------------------------------------------------------------------------
// Flash attention BQ=128, term-major mma order (same-acc distance 4).
// ---------------------------------------------------------------------------
__global__ __launch_bounds__(256, 2) void flash_bq128(
    const float* __restrict__ qkv,
    const __nv_bfloat16* __restrict__ kvh, const __nv_bfloat16* __restrict__ kvl,
    __nv_bfloat16* __restrict__ ctxh, __nv_bfloat16* __restrict__ ctxl)
{
    extern __shared__ char sf[];
    const unsigned sb = saddr(sf);

    const int tid  = threadIdx.x;
    const int lane = tid & 31;
    const int w    = tid >> 5;
    const int g = lane >> 2, t = lane & 3;
    const int mi = lane >> 3, rr = lane & 7;
    const int aro = ((mi & 1) << 3) + rr, aco = (mi >> 1) << 3;
    const int kno = ((mi >> 1) << 3) + rr, kko = (mi & 1) << 3;
    const int vro = ((mi & 1) << 3) + rr, vco = (mi >> 1) << 3;
    const int r0 = (w << 4) + g, r1 = r0 + 8;

    const int bh = blockIdx.y;
    const int b = bh >> 4, h = bh & 15;
    const int qt = gridDim.x - 1 - blockIdx.x;
    const int q0 = qt << 7;

    const float* Qg = qkv + (size_t)(b * S_ + q0) * D3_ + h * 64;
    const __nv_bfloat16* Kgh = kvh + ((size_t)(b * 2    ) * H_ + h) * T_ * 64;
    const __nv_bfloat16* Kgl = kvl + ((size_t)(b * 2    ) * H_ + h) * T_ * 64;
    const __nv_bfloat16* Vgh = kvh + ((size_t)(b * 2 + 1) * H_ + h) * T_ * 64;
    const __nv_bfloat16* Vgl = kvl + ((size_t)(b * 2 + 1) * H_ + h) * T_ * 64;

    __nv_bfloat16* sQh = (__nv_bfloat16*)(sf + 73728);
    __nv_bfloat16* sQl = (__nv_bfloat16*)(sf + 92160);
    const unsigned sqa = sb + 73728;

    const float QSCALE = 0.125f * 1.4426950408889634f;
#pragma unroll
    for (int p = 0; p < 8; p++) {
        int idx = tid + (p << 8);
        int r = idx >> 4, c4 = (idx & 15) << 2;
        float4 v = *(const float4*)&Qg[(size_t)r * D3_ + c4];
        v.x *= QSCALE; v.y *= QSCALE; v.z *= QSCALE; v.w *= QSCALE;
        unsigned h01, l01, h23, l23;
        split2(v.x, v.y, h01, l01);
        split2(v.z, v.w, h23, l23);
        *(uint2*)&sQh[r * 72 + c4] = make_uint2(h01, h23);
        *(uint2*)&sQl[r * 72 + c4] = make_uint2(l01, l23);
    }

    auto issueKV = [&](int k0, int st) {
        unsigned b0 = sb + st * 36864;
        size_t gr = (size_t)k0 * 128;
#pragma unroll
        for (int p = 0; p < 2; p++) {
            int idx = tid + (p << 8);
            int r = idx >> 3, cb = (idx & 7) << 4;
            unsigned d = b0 + r * 144 + cb;
            size_t go = gr + (size_t)r * 128 + cb;
            cp16(d,         (const char*)Kgh + go);
            cp16(d +  9216, (const char*)Kgl + go);
            cp16(d + 18432, (const char*)Vgh + go);
            cp16(d + 27648, (const char*)Vgl + go);
        }
    };

    float m0 = -1e30f, m1 = -1e30f, l0 = 0.f, l1 = 0.f;
    float o[8][4];
#pragma unroll
    for (int nt = 0; nt < 8; nt++)
#pragma unroll
        for (int r = 0; r < 4; r++) o[nt][r] = 0.f;

    __syncthreads();
    const int nIter = (P_ >> 6) + (q0 >> 6) + 2;
    issueKV(0, 0);
    cp_commit();

    for (int it = 0; it < nIter; it++) {
        if (it + 1 < nIter) { issueKV((it + 1) << 6, (it + 1) & 1); cp_commit(); cp_wait<1>(); }
        else                { cp_wait<0>(); }
        __syncthreads();

        if (it + 1 < nIter || w >= 4) {
            unsigned kb = sb + (it & 1) * 36864;

            // ---- S = Q K^T  (pairs of ntp; term-major, distance 4) ----
            float s[8][4];
#pragma unroll
            for (int nt = 0; nt < 8; nt++)
#pragma unroll
                for (int r = 0; r < 4; r++) s[nt][r] = 0.f;

#pragma unroll
            for (int kc = 0; kc < 4; kc++) {
                unsigned qh[4], ql[4];
                unsigned qoff = sqa + (unsigned)((((w << 4) + aro) * 72 + (kc << 4) + aco) * 2);
                ldsm_x4(qh, qoff);
                ldsm_x4(ql, qoff + 18432);
#pragma unroll
                for (int npp = 0; npp < 2; npp++) {
                    unsigned b0h[4], b0l[4], b1h[4], b1l[4];
                    unsigned off0 = kb + (unsigned)(((((npp << 1)    << 4) + kno) * 72 + (kc << 4) + kko) * 2);
                    unsigned off1 = kb + (unsigned)(((((npp << 1) + 1 << 4) + kno) * 72 + (kc << 4) + kko) * 2);
                    ldsm_x4(b0h, off0);
                    ldsm_x4(b0l, off0 + 9216);
                    ldsm_x4(b1h, off1);
                    ldsm_x4(b1l, off1 + 9216);
                    const int n0 = npp << 2;
                    // term 1: 4 distinct accs
                    mma_bf16(s[n0],     qh, b0h);
                    mma_bf16(s[n0 + 1], qh, b0h + 2);
                    mma_bf16(s[n0 + 2], qh, b1h);
                    mma_bf16(s[n0 + 3], qh, b1h + 2);
                    // term 2
                    mma_bf16(s[n0],     qh, b0l);
                    mma_bf16(s[n0 + 1], qh, b0l + 2);
                    mma_bf16(s[n0 + 2], qh, b1l);
                    mma_bf16(s[n0 + 3], qh, b1l + 2);
                    // term 3
                    mma_bf16(s[n0],     ql, b0h);
                    mma_bf16(s[n0 + 1], ql, b0h + 2);
                    mma_bf16(s[n0 + 2], ql, b1h);
                    mma_bf16(s[n0 + 3], ql, b1h + 2);
                }
            }

            const int kRel = (it << 6) - P_ - q0;
            if (kRel + 63 > 0) {
#pragma unroll
                for (int nt = 0; nt < 8; nt++) {
                    int c0 = (nt << 3) + 2 * t + kRel;
                    if (c0     > r0) s[nt][0] = -1e30f;
                    if (c0 + 1 > r0) s[nt][1] = -1e30f;
                    if (c0     > r1) s[nt][2] = -1e30f;
                    if (c0 + 1 > r1) s[nt][3] = -1e30f;
                }
            }

            float mx0 = -1e30f, mx1 = -1e30f;
#pragma unroll
            for (int nt = 0; nt < 8; nt++) {
                mx0 = fmaxf(mx0, fmaxf(s[nt][0], s[nt][1]));
                mx1 = fmaxf(mx1, fmaxf(s[nt][2], s[nt][3]));
            }
            mx0 = fmaxf(mx0, __shfl_xor_sync(0xffffffffu, mx0, 1));
            mx0 = fmaxf(mx0, __shfl_xor_sync(0xffffffffu, mx0, 2));
            mx1 = fmaxf(mx1, __shfl_xor_sync(0xffffffffu, mx1, 1));
            mx1 = fmaxf(mx1, __shfl_xor_sync(0xffffffffu, mx1, 2));
            float nm0 = fmaxf(m0, mx0), nm1 = fmaxf(m1, mx1);
            float sc0 = exp2f(m0 - nm0), sc1 = exp2f(m1 - nm1);
            float rs0 = 0.f, rs1 = 0.f;
#pragma unroll
            for (int nt = 0; nt < 8; nt++) {
                s[nt][0] = exp2f(s[nt][0] - nm0); rs0 += s[nt][0];
                s[nt][1] = exp2f(s[nt][1] - nm0); rs0 += s[nt][1];
                s[nt][2] = exp2f(s[nt][2] - nm1); rs1 += s[nt][2];
                s[nt][3] = exp2f(s[nt][3] - nm1); rs1 += s[nt][3];
            }
            rs0 += __shfl_xor_sync(0xffffffffu, rs0, 1);
            rs0 += __shfl_xor_sync(0xffffffffu, rs0, 2);
            rs1 += __shfl_xor_sync(0xffffffffu, rs1, 1);
            rs1 += __shfl_xor_sync(0xffffffffu, rs1, 2);
            l0 = l0 * sc0 + rs0;  m0 = nm0;
            l1 = l1 * sc1 + rs1;  m1 = nm1;
#pragma unroll
            for (int nt = 0; nt < 8; nt++) {
                o[nt][0] *= sc0; o[nt][1] *= sc0;
                o[nt][2] *= sc1; o[nt][3] *= sc1;
            }

            // ---- O += P V  (pairs of ntp; term-major, distance 4) ----
#pragma unroll
            for (int kc = 0; kc < 4; kc++) {
                unsigned ah[4], al[4];
                split2(s[2*kc    ][0], s[2*kc    ][1], ah[0], al[0]);
                split2(s[2*kc    ][2], s[2*kc    ][3], ah[1], al[1]);
                split2(s[2*kc + 1][0], s[2*kc + 1][1], ah[2], al[2]);
                split2(s[2*kc + 1][2], s[2*kc + 1][3], ah[3], al[3]);
#pragma unroll
                for (int npp = 0; npp < 2; npp++) {
                    unsigned v0h[4], v0l[4], v1h[4], v1l[4];
                    unsigned off0 = kb + 18432 + (unsigned)((((kc << 4) + vro) * 72 + (((npp << 1)    ) << 4) + vco) * 2);
                    unsigned off1 = kb + 18432 + (unsigned)((((kc << 4) + vro) * 72 + (((npp << 1) + 1) << 4) + vco) * 2);
                    ldsm_x4_t(v0h, off0);
                    ldsm_x4_t(v0l, off0 + 9216);
                    ldsm_x4_t(v1h, off1);
                    ldsm_x4_t(v1l, off1 + 9216);
                    const int n0 = npp << 2;
                    // term 1
                    mma_bf16(o[n0],     ah, v0h);
                    mma_bf16(o[n0 + 1], ah, v0h + 2);
                    mma_bf16(o[n0 + 2], ah, v1h);
                    mma_bf16(o[n0 + 3], ah, v1h + 2);
                    // term 2
                    mma_bf16(o[n0],     ah, v0l);
                    mma_bf16(o[n0 + 1], ah, v0l + 2);
                    mma_bf16(o[n0 + 2], ah, v1l);
                    mma_bf16(o[n0 + 3], ah, v1l + 2);
                    // term 3
                    mma_bf16(o[n0],     al, v0h);
                    mma_bf16(o[n0 + 1], al, v0h + 2);
                    mma_bf16(o[n0 + 2], al, v1h);
                    mma_bf16(o[n0 + 3], al, v1h + 2);
                }
            }
        }
        __syncthreads();
    }

    float inv0 = 1.f / l0, inv1 = 1.f / l1;
    size_t o0 = (size_t)(b * S_ + q0 + r0) * D_ + h * 64;
    size_t o1 = (size_t)(b * S_ + q0 + r1) * D_ + h * 64;
#pragma unroll
    for (int nt = 0; nt < 8; nt++) {
        int c0 = (nt << 3) + 2 * t;
        unsigned hh, ll;
        split2(o[nt][0] * inv0, o[nt][1] * inv0, hh, ll);
        *(unsigned*)&ctxh[o0 + c0] = hh;
        *(unsigned*)&ctxl[o0 + c0] = ll;
        split2(o[nt][2] * inv1, o[nt][3] * inv1, hh, ll);
        *(unsigned*)&ctxh[o1 + c0] = hh;
        *(unsigned*)&ctxl[o1 + c0] = ll;
    }
}

// ---------------------------------------------------------------------------
// Launch
// ---------------------------------------------------------------------------
extern "C" void kernel_launch(void* const* d_in, const int* in_sizes, int n_in,
                              void* d_out, int out_size)
{
    const float* x      = (const float*)d_in[0];
    // d_in[1] = mask: exactly causal -> applied analytically
    const float* past   = (const float*)d_in[2];
    const float* w_attn = (const float*)d_in[3];
    const float* b_attn = (const float*)d_in[4];
    const float* w_proj = (const float*)d_in[5];
    const float* b_proj = (const float*)d_in[6];

    float* out     = (float*)d_out;
    float* present = out + OUT_OFF;

    void* p;
    float* qkv;
    __nv_bfloat16 *xh, *xl, *ch, *cl, *kvh, *kvl, *wah, *wal, *wph, *wpl;
    cudaGetSymbolAddress(&p, g_qkv); qkv = (float*)p;
    cudaGetSymbolAddress(&p, g_xh);  xh  = (__nv_bfloat16*)p;
    cudaGetSymbolAddress(&p, g_xl);  xl  = (__nv_bfloat16*)p;
    cudaGetSymbolAddress(&p, g_ch);  ch  = (__nv_bfloat16*)p;
    cudaGetSymbolAddress(&p, g_cl);  cl  = (__nv_bfloat16*)p;
    cudaGetSymbolAddress(&p, g_kvh); kvh = (__nv_bfloat16*)p;
    cudaGetSymbolAddress(&p, g_kvl); kvl = (__nv_bfloat16*)p;
    cudaGetSymbolAddress(&p, g_wah); wah = (__nv_bfloat16*)p;
    cudaGetSymbolAddress(&p, g_wal); wal = (__nv_bfloat16*)p;
    cudaGetSymbolAddress(&p, g_wph); wph = (__nv_bfloat16*)p;
    cudaGetSymbolAddress(&p, g_wpl); wpl = (__nv_bfloat16*)p;

    const int GEMM_SMEM  = 2 * 40960;          // 81920
    const int FLASH_SMEM = 2 * 36864 + 36864;  // 110592
    cudaFuncSetAttribute(gemm_presplit,
                         cudaFuncAttributeMaxDynamicSharedMemorySize, GEMM_SMEM);
    cudaFuncSetAttribute(flash_bq128,
                         cudaFuncAttributeMaxDynamicSharedMemorySize, FLASH_SMEM);

    // 0. pre-split inputs/weights
    split_x<<<(B_ * S_ * D_ / 4) / 256, 256>>>((const float4*)x, xh, xl);
    split_w<<<dim3(D_ / 32, D3_ / 32), 256>>>(w_attn, wah, wal, D_, D3_);
    split_w<<<dim3(D_ / 32, D_  / 32), 256>>>(w_proj, wph, wpl, D_, D_);

    // 1. QKV projection
    gemm_presplit<<<dim3(D3_ / 128, (B_ * S_) / 128), 256, GEMM_SMEM>>>(
        xh, xl, wah, wal, b_attn, qkv, B_ * S_, D3_, D_);

    // 2. present (f32, into d_out) + K/V hi/lo split
    build_present<<<(B_ * 2 * H_ * T_ * 16) / 256, 256>>>(
        (const float4*)past, (const float4*)qkv, (float4*)present, kvh, kvl);

    // 3. flash attention -> ctx hi/lo
    flash_bq128<<<dim3(S_ / 128, B_ * H_), 256, FLASH_SMEM>>>(
        qkv, kvh, kvl, ch, cl);

    // 4. output projection
    gemm_presplit<<<dim3(D_ / 128, (B_ * S_) / 128), 256, GEMM_SMEM>>>(
        ch, cl, wph, wpl, b_proj, out, B_ * S_, D_, D_);
}

// round 9
// speedup vs baseline: 1.0299x; 1.0161x over previous
#include <cuda_runtime.h>
#include <cuda_bf16.h>

// Problem constants
#define B_   2
#define S_   2048
#define D_   1024
#define H_   16
#define P_   2048
#define T_   4096
#define D3_  3072
#define OUT_OFF (B_*S_*D_)

// ---------------------------------------------------------------------------
// Scratch (device globals)
// ---------------------------------------------------------------------------
__device__ float g_qkv[(size_t)B_ * S_ * D3_];
__device__ __nv_bfloat16 g_xh [(size_t)B_ * S_ * D_];
__device__ __nv_bfloat16 g_xl [(size_t)B_ * S_ * D_];
__device__ __nv_bfloat16 g_ch [(size_t)B_ * S_ * D_];
__device__ __nv_bfloat16 g_cl [(size_t)B_ * S_ * D_];
__device__ __nv_bfloat16 g_kvh[(size_t)B_ * 2 * H_ * T_ * 64];
__device__ __nv_bfloat16 g_kvl[(size_t)B_ * 2 * H_ * T_ * 64];
__device__ __nv_bfloat16 g_wah[(size_t)D3_ * D_];
__device__ __nv_bfloat16 g_wal[(size_t)D3_ * D_];
__device__ __nv_bfloat16 g_wph[(size_t)D_ * D_];
__device__ __nv_bfloat16 g_wpl[(size_t)D_ * D_];

// ---------------------------------------------------------------------------
// Primitives
// ---------------------------------------------------------------------------
__device__ __forceinline__ void mma_bf16(float* d, const unsigned* a, const unsigned* b) {
    asm volatile(
        "mma.sync.aligned.m16n8k16.row.col.f32.bf16.bf16.f32 "
        "{%0,%1,%2,%3}, {%4,%5,%6,%7}, {%8,%9}, {%0,%1,%2,%3};\n"
        : "+f"(d[0]), "+f"(d[1]), "+f"(d[2]), "+f"(d[3])
        : "r"(a[0]), "r"(a[1]), "r"(a[2]), "r"(a[3]), "r"(b[0]), "r"(b[1]));
}
__device__ __forceinline__ void ldsm_x4(unsigned* r, unsigned addr) {
    asm volatile("ldmatrix.sync.aligned.m8n8.x4.shared.b16 {%0,%1,%2,%3}, [%4];"
        : "=r"(r[0]), "=r"(r[1]), "=r"(r[2]), "=r"(r[3]) : "r"(addr));
}
__device__ __forceinline__ void ldsm_x4_t(unsigned* r, unsigned addr) {
    asm volatile("ldmatrix.sync.aligned.m8n8.x4.trans.shared.b16 {%0,%1,%2,%3}, [%4];"
        : "=r"(r[0]), "=r"(r[1]), "=r"(r[2]), "=r"(r[3]) : "r"(addr));
}
__device__ __forceinline__ void split2(float x, float y, unsigned& hi, unsigned& lo) {
    __nv_bfloat162 h = __floats2bfloat162_rn(x, y);
    float rx = x - __bfloat162float(h.x);
    float ry = y - __bfloat162float(h.y);
    __nv_bfloat162 l = __floats2bfloat162_rn(rx, ry);
    hi = *(unsigned*)&h;
    lo = *(unsigned*)&l;
}
__device__ __forceinline__ unsigned saddr(const void* p) {
    return (unsigned)__cvta_generic_to_shared(p);
}
__device__ __forceinline__ void cp16(unsigned dst, const void* src) {
    asm volatile("cp.async.cg.shared.global [%0], [%1], 16;\n" :: "r"(dst), "l"(src));
}
__device__ __forceinline__ void cp_commit() {
    asm volatile("cp.async.commit_group;\n");
}
template<int N> __device__ __forceinline__ void cp_wait() {
    asm volatile("cp.async.wait_group %0;\n" :: "n"(N));
}

// ---------------------------------------------------------------------------
// Split x -> bf16 hi/lo
// ---------------------------------------------------------------------------
__global__ void split_x(const float4* __restrict__ x4,
                        __nv_bfloat16* __restrict__ xh,
                        __nv_bfloat16* __restrict__ xl)
{
    int i = blockIdx.x * blockDim.x + threadIdx.x;
    float4 v = x4[i];
    unsigned h01, l01, h23, l23;
    split2(v.x, v.y, h01, l01);
    split2(v.z, v.w, h23, l23);
    *(uint2*)&xh[(size_t)i * 4] = make_uint2(h01, h23);
    *(uint2*)&xl[(size_t)i * 4] = make_uint2(l01, l23);
}

// ---------------------------------------------------------------------------
// Weight split+transpose: w[K][N] f32 -> wt_hi/lo [N][K] bf16
// ---------------------------------------------------------------------------
__global__ __launch_bounds__(256) void split_w(
    const float* __restrict__ w, __nv_bfloat16* __restrict__ th,
    __nv_bfloat16* __restrict__ tl, int K, int N)
{
    __shared__ float t[32][33];
    const int k0 = blockIdx.x << 5, n0 = blockIdx.y << 5;
    const int c = threadIdx.x & 31, r8 = threadIdx.x >> 5;
#pragma unroll
    for (int i = 0; i < 4; i++) {
        int k = r8 + (i << 3);
        t[k][c] = w[(size_t)(k0 + k) * N + n0 + c];
    }
    __syncthreads();
#pragma unroll
    for (int i = 0; i < 4; i++) {
        int n = r8 + (i << 3);
        float v = t[c][n];
        __nv_bfloat16 h = __float2bfloat16(v);
        th[(size_t)(n0 + n) * K + k0 + c] = h;
        tl[(size_t)(n0 + n) * K + k0 + c] = __float2bfloat16(v - __bfloat162float(h));
    }
}

// ---------------------------------------------------------------------------
// Build `present` f32 + split K/V bf16 hi/lo
// ---------------------------------------------------------------------------
__global__ void build_present(const float4* __restrict__ past4,
                              const float4* __restrict__ qkv4,
                              float4* __restrict__ pres4,
                              __nv_bfloat16* __restrict__ kvh,
                              __nv_bfloat16* __restrict__ kvl)
{
    int i = blockIdx.x * blockDim.x + threadIdx.x;
    int d4  = i & 15;
    int j   = i >> 4;
    int p   = j & (T_ - 1);
    int chh = j >> 12;
    int h = chh & (H_ - 1);
    int c = (chh >> 4) & 1;
    int b = chh >> 5;

    float4 v;
    if (p < P_) {
        v = past4[(((size_t)((b * 2 + c) * H_ + h) * P_ + p) << 4) + d4];
    } else {
        int s = p - P_;
        v = qkv4[(size_t)(b * S_ + s) * 768 + (c + 1) * 256 + h * 16 + d4];
    }
    pres4[i] = v;
    unsigned h01, l01, h23, l23;
    split2(v.x, v.y, h01, l01);
    split2(v.z, v.w, h23, l23);
    *(uint2*)&kvh[(size_t)i * 4] = make_uint2(h01, h23);
    *(uint2*)&kvl[(size_t)i * 4] = make_uint2(l01, l23);
}

// ---------------------------------------------------------------------------
// GEMM, pre-split operands, cp.async 2-stage (unchanged from R8).
// ---------------------------------------------------------------------------
__global__ __launch_bounds__(256, 2) void gemm_presplit(
    const __nv_bfloat16* __restrict__ Ah, const __nv_bfloat16* __restrict__ Al,
    const __nv_bfloat16* __restrict__ Wh, const __nv_bfloat16* __restrict__ Wl,
    const float* __restrict__ bias, float* __restrict__ C,
    int M, int N, int K)
{
    extern __shared__ char sg[];
    const unsigned sb = saddr(sg);

    const int tid  = threadIdx.x;
    const int lane = tid & 31;
    const int warp = tid >> 5;
    const int g = lane >> 2, t = lane & 3;
    const int mi = lane >> 3, rr = lane & 7;
    const int aro = ((mi & 1) << 3) + rr, aco = (mi >> 1) << 3;
    const int bno = ((mi >> 1) << 3) + rr, bko = (mi & 1) << 3;
    const int wm = warp >> 2, wn = warp & 3;
    const int bm = blockIdx.y << 7, bn = blockIdx.x << 7;

    auto issue = [&](int k0, int st) {
        unsigned b0 = sb + st * 40960;
#pragma unroll
        for (int p = 0; p < 2; p++) {
            int idx = tid + (p << 8);
            int r = idx >> 2, cb = (idx & 3) << 4;
            size_t ga = ((size_t)(bm + r) * K + k0) * 2 + cb;
            size_t gb = ((size_t)(bn + r) * K + k0) * 2 + cb;
            unsigned d = b0 + r * 80 + cb;
            cp16(d,         (const char*)Ah + ga);
            cp16(d + 10240, (const char*)Al + ga);
            cp16(d + 20480, (const char*)Wh + gb);
            cp16(d + 30720, (const char*)Wl + gb);
        }
    };

    float acc[4][4][4];
#pragma unroll
    for (int i = 0; i < 4; i++)
#pragma unroll
        for (int j = 0; j < 4; j++)
#pragma unroll
            for (int r = 0; r < 4; r++) acc[i][j][r] = 0.f;

    const int nK = K >> 5;
    issue(0, 0);
    cp_commit();

    for (int it = 0; it < nK; it++) {
        if (it + 1 < nK) { issue((it + 1) << 5, (it + 1) & 1); cp_commit(); cp_wait<1>(); }
        else             { cp_wait<0>(); }
        __syncthreads();

        unsigned b0 = sb + (it & 1) * 40960;
#pragma unroll
        for (int kc = 0; kc < 2; kc++) {
            unsigned ah[4][4], al[4][4];
#pragma unroll
            for (int mt = 0; mt < 4; mt++) {
                unsigned off = b0 + (unsigned)((((wm << 6) + (mt << 4) + aro) * 40 + (kc << 4) + aco) * 2);
                ldsm_x4(ah[mt], off);
                ldsm_x4(al[mt], off + 10240);
            }
#pragma unroll
            for (int ntp = 0; ntp < 2; ntp++) {
                unsigned bh[4], bl[4];
                unsigned off = b0 + 20480 + (unsigned)((((wn << 5) + (ntp << 4) + bno) * 40 + (kc << 4) + bko) * 2);
                ldsm_x4(bh, off);
                ldsm_x4(bl, off + 10240);
                const int n0 = ntp << 1;
#pragma unroll
                for (int mt = 0; mt < 4; mt++) {
                    mma_bf16(acc[mt][n0],     ah[mt], bh);
                    mma_bf16(acc[mt][n0 + 1], ah[mt], bh + 2);
                }
#pragma unroll
                for (int mt = 0; mt < 4; mt++) {
                    mma_bf16(acc[mt][n0],     ah[mt], bl);
                    mma_bf16(acc[mt][n0 + 1], ah[mt], bl + 2);
                }
#pragma unroll
                for (int mt = 0; mt < 4; mt++) {
                    mma_bf16(acc[mt][n0],     al[mt], bh);
                    mma_bf16(acc[mt][n0 + 1], al[mt], bh + 2);
                }
            }
        }
        __syncthreads();
    }

#pragma unroll
    for (int mt = 0; mt < 4; mt++) {
#pragma unroll
        for (int nt = 0; nt < 4; nt++) {
            int row = bm + (wm << 6) + (mt << 4) + g;
            int col = bn + (wn << 5) + (nt << 3) + 2 * t;
            float bx = bias[col], by = bias[col + 1];
            *(float2*)&C[(size_t)row * N + col] =
                make_float2(acc[mt][nt][0] + bx, acc[mt][nt][1] + by);
            *(float2*)&C[(size_t)(row + 8) * N + col] =
                make_float2(acc[mt][nt][2] + bx, acc[mt][nt][3] + by);
        }
    }
}

// ---------------------------------------------------------------------------
// Flash attention BQ=128, 128 threads: 4 warps x 32 q-rows (2 m-tiles/warp).
// Each K/V fragment load now feeds 2 m-tiles -> smem reads per HMMA drop
// 384B -> ~107B (the binding resource per R8 analysis).
// smem layout identical to R8 (110592 B): KV stages at 0/36864, Q at 73728.
// ---------------------------------------------------------------------------
__global__ __launch_bounds__(128, 2) void flash_m32(
    const float* __restrict__ qkv,
    const __nv_bfloat16* __restrict__ kvh, const __nv_bfloat16* __restrict__ kvl,
    __nv_bfloat16* __restrict__ ctxh, __nv_bfloat16* __restrict__ ctxl)
{
    extern __shared__ char sf[];
    const unsigned sb = saddr(sf);

    const int tid  = threadIdx.x;
    const int lane = tid & 31;
    const int w    = tid >> 5;            // warp 0..3 -> rows 32w..32w+31
    const int g = lane >> 2, t = lane & 3;
    const int mi = lane >> 3, rr = lane & 7;
    const int aro = ((mi & 1) << 3) + rr, aco = (mi >> 1) << 3;
    const int kno = ((mi >> 1) << 3) + rr, kko = (mi & 1) << 3;
    const int vro = ((mi & 1) << 3) + rr, vco = (mi >> 1) << 3;

    const int bh = blockIdx.y;
    const int b = bh >> 4, h = bh & 15;
    const int qt = gridDim.x - 1 - blockIdx.x;
    const int q0 = qt << 7;

    const float* Qg = qkv + (size_t)(b * S_ + q0) * D3_ + h * 64;
    const __nv_bfloat16* Kgh = kvh + ((size_t)(b * 2    ) * H_ + h) * T_ * 64;
    const __nv_bfloat16* Kgl = kvl + ((size_t)(b * 2    ) * H_ + h) * T_ * 64;
    const __nv_bfloat16* Vgh = kvh + ((size_t)(b * 2 + 1) * H_ + h) * T_ * 64;
    const __nv_bfloat16* Vgl = kvl + ((size_t)(b * 2 + 1) * H_ + h) * T_ * 64;

    __nv_bfloat16* sQh = (__nv_bfloat16*)(sf + 73728);
    __nv_bfloat16* sQl = (__nv_bfloat16*)(sf + 92160);
    const unsigned sqa = sb + 73728;

    // ---- Q: load f32, scale by log2(e)/8, split (2048 float4, 128 thr) ----
    const float QSCALE = 0.125f * 1.4426950408889634f;
#pragma unroll
    for (int p = 0; p < 16; p++) {
        int idx = tid + (p << 7);
        int r = idx >> 4, c4 = (idx & 15) << 2;
        float4 v = *(const float4*)&Qg[(size_t)r * D3_ + c4];
        v.x *= QSCALE; v.y *= QSCALE; v.z *= QSCALE; v.w *= QSCALE;
        unsigned h01, l01, h23, l23;
        split2(v.x, v.y, h01, l01);
        split2(v.z, v.w, h23, l23);
        *(uint2*)&sQh[r * 72 + c4] = make_uint2(h01, h23);
        *(uint2*)&sQl[r * 72 + c4] = make_uint2(l01, l23);
    }

    auto issueKV = [&](int k0, int st) {
        unsigned b0 = sb + st * 36864;
        size_t gr = (size_t)k0 * 128;
#pragma unroll
        for (int p = 0; p < 4; p++) {
            int idx = tid + (p << 7);     // 0..511 chunks
            int r = idx >> 3, cb = (idx & 7) << 4;
            unsigned d = b0 + r * 144 + cb;
            size_t go = gr + (size_t)r * 128 + cb;
            cp16(d,         (const char*)Kgh + go);
            cp16(d +  9216, (const char*)Kgl + go);
            cp16(d + 18432, (const char*)Vgh + go);
            cp16(d + 27648, (const char*)Vgl + go);
        }
    };

    float m[2][2], l[2][2];
    float o[2][8][4];
#pragma unroll
    for (int mt = 0; mt < 2; mt++) {
        m[mt][0] = m[mt][1] = -1e30f;
        l[mt][0] = l[mt][1] = 0.f;
#pragma unroll
        for (int nt = 0; nt < 8; nt++)
#pragma unroll
            for (int r = 0; r < 4; r++) o[mt][nt][r] = 0.f;
    }

    __syncthreads();
    const int nIter = (P_ >> 6) + (q0 >> 6) + 2;
    issueKV(0, 0);
    cp_commit();

    for (int it = 0; it < nIter; it++) {
        if (it + 1 < nIter) { issueKV((it + 1) << 6, (it + 1) & 1); cp_commit(); cp_wait<1>(); }
        else                { cp_wait<0>(); }
        __syncthreads();

        const int kRel = (it << 6) - P_ - q0;
        // warp fully masked iff its max row (32w+31) < min col (kRel)
        if (kRel <= (w << 5) + 31) {
            unsigned kb = sb + (it & 1) * 36864;

            // ---- S = Q K^T ----
            float s[2][8][4];
#pragma unroll
            for (int mt = 0; mt < 2; mt++)
#pragma unroll
                for (int nt = 0; nt < 8; nt++)
#pragma unroll
                    for (int r = 0; r < 4; r++) s[mt][nt][r] = 0.f;

#pragma unroll
            for (int kc = 0; kc < 4; kc++) {
                unsigned qh[2][4], ql[2][4];
#pragma unroll
                for (int mt = 0; mt < 2; mt++) {
                    unsigned qoff = sqa + (unsigned)((((w << 5) + (mt << 4) + aro) * 72 + (kc << 4) + aco) * 2);
                    ldsm_x4(qh[mt], qoff);
                    ldsm_x4(ql[mt], qoff + 18432);
                }
#pragma unroll
                for (int npp = 0; npp < 2; npp++) {
                    unsigned b0h[4], b0l[4], b1h[4], b1l[4];
                    unsigned off0 = kb + (unsigned)(((((npp << 1)     ) << 4) + kno) * 72 * 2 + ((kc << 4) + kko) * 2);
                    unsigned off1 = kb + (unsigned)(((((npp << 1) + 1) << 4) + kno) * 72 * 2 + ((kc << 4) + kko) * 2);
                    ldsm_x4(b0h, off0);
                    ldsm_x4(b0l, off0 + 9216);
                    ldsm_x4(b1h, off1);
                    ldsm_x4(b1l, off1 + 9216);
                    const int n0 = npp << 2;
                    // term 1 (qh * bh): 8 distinct accumulators
#pragma unroll
                    for (int mt = 0; mt < 2; mt++) {
                        mma_bf16(s[mt][n0],     qh[mt], b0h);
                        mma_bf16(s[mt][n0 + 1], qh[mt], b0h + 2);
                        mma_bf16(s[mt][n0 + 2], qh[mt], b1h);
                        mma_bf16(s[mt][n0 + 3], qh[mt], b1h + 2);
                    }
                    // term 2 (qh * bl)
#pragma unroll
                    for (int mt = 0; mt < 2; mt++) {
                        mma_bf16(s[mt][n0],     qh[mt], b0l);
                        mma_bf16(s[mt][n0 + 1], qh[mt], b0l + 2);
                        mma_bf16(s[mt][n0 + 2], qh[mt], b1l);
                        mma_bf16(s[mt][n0 + 3], qh[mt], b1l + 2);
                    }
                    // term 3 (ql * bh)
#pragma unroll
                    for (int mt = 0; mt < 2; mt++) {
                        mma_bf16(s[mt][n0],     ql[mt], b0h);
                        mma_bf16(s[mt][n0 + 1], ql[mt], b0h + 2);
                        mma_bf16(s[mt][n0 + 2], ql[mt], b1h);
                        mma_bf16(s[mt][n0 + 3], ql[mt], b1h + 2);
                    }
                }
            }

            // ---- causal mask (last two iterations only) ----
            if (kRel + 63 > 0) {
#pragma unroll
                for (int mt = 0; mt < 2; mt++) {
                    int r0 = (w << 5) + (mt << 4) + g, r1 = r0 + 8;
#pragma unroll
                    for (int nt = 0; nt < 8; nt++) {
                        int c0 = (nt << 3) + 2 * t + kRel;
                        if (c0     > r0) s[mt][nt][0] = -1e30f;
                        if (c0 + 1 > r0) s[mt][nt][1] = -1e30f;
                        if (c0     > r1) s[mt][nt][2] = -1e30f;
                        if (c0 + 1 > r1) s[mt][nt][3] = -1e30f;
                    }
                }
            }

            // ---- online softmax (log2 domain) ----
#pragma unroll
            for (int mt = 0; mt < 2; mt++) {
                float mx0 = -1e30f, mx1 = -1e30f;
#pragma unroll
                for (int nt = 0; nt < 8; nt++) {
                    mx0 = fmaxf(mx0, fmaxf(s[mt][nt][0], s[mt][nt][1]));
                    mx1 = fmaxf(mx1, fmaxf(s[mt][nt][2], s[mt][nt][3]));
                }
                mx0 = fmaxf(mx0, __shfl_xor_sync(0xffffffffu, mx0, 1));
                mx0 = fmaxf(mx0, __shfl_xor_sync(0xffffffffu, mx0, 2));
                mx1 = fmaxf(mx1, __shfl_xor_sync(0xffffffffu, mx1, 1));
                mx1 = fmaxf(mx1, __shfl_xor_sync(0xffffffffu, mx1, 2));
                float nm0 = fmaxf(m[mt][0], mx0), nm1 = fmaxf(m[mt][1], mx1);
                float sc0 = exp2f(m[mt][0] - nm0), sc1 = exp2f(m[mt][1] - nm1);
                float rs0 = 0.f, rs1 = 0.f;
#pragma unroll
                for (int nt = 0; nt < 8; nt++) {
                    s[mt][nt][0] = exp2f(s[mt][nt][0] - nm0); rs0 += s[mt][nt][0];
                    s[mt][nt][1] = exp2f(s[mt][nt][1] - nm0); rs0 += s[mt][nt][1];
                    s[mt][nt][2] = exp2f(s[mt][nt][2] - nm1); rs1 += s[mt][nt][2];
                    s[mt][nt][3] = exp2f(s[mt][nt][3] - nm1); rs1 += s[mt][nt][3];
                }
                rs0 += __shfl_xor_sync(0xffffffffu, rs0, 1);
                rs0 += __shfl_xor_sync(0xffffffffu, rs0, 2);
                rs1 += __shfl_xor_sync(0xffffffffu, rs1, 1);
                rs1 += __shfl_xor_sync(0xffffffffu, rs1, 2);
                l[mt][0] = l[mt][0] * sc0 + rs0;  m[mt][0] = nm0;
                l[mt][1] = l[mt][1] * sc1 + rs1;  m[mt][1] = nm1;
#pragma unroll
                for (int nt = 0; nt < 8; nt++) {
                    o[mt][nt][0] *= sc0; o[mt][nt][1] *= sc0;
                    o[mt][nt][2] *= sc1; o[mt][nt][3] *= sc1;
                }
            }

            // ---- O += P V ----
#pragma unroll
            for (int kc = 0; kc < 4; kc++) {
                unsigned ah[2][4], al[2][4];
#pragma unroll
                for (int mt = 0; mt < 2; mt++) {
                    split2(s[mt][2*kc    ][0], s[mt][2*kc    ][1], ah[mt][0], al[mt][0]);
                    split2(s[mt][2*kc    ][2], s[mt][2*kc    ][3], ah[mt][1], al[mt][1]);
                    split2(s[mt][2*kc + 1][0], s[mt][2*kc + 1][1], ah[mt][2], al[mt][2]);
                    split2(s[mt][2*kc + 1][2], s[mt][2*kc + 1][3], ah[mt][3], al[mt][3]);
                }
#pragma unroll
                for (int npp = 0; npp < 2; npp++) {
                    unsigned v0h[4], v0l[4], v1h[4], v1l[4];
                    unsigned off0 = kb + 18432 + (unsigned)((((kc << 4) + vro) * 72 + (((npp << 1)    ) << 4) + vco) * 2);
                    unsigned off1 = kb + 18432 + (unsigned)((((kc << 4) + vro) * 72 + (((npp << 1) + 1) << 4) + vco) * 2);
                    ldsm_x4_t(v0h, off0);
                    ldsm_x4_t(v0l, off0 + 9216);
                    ldsm_x4_t(v1h, off1);
                    ldsm_x4_t(v1l, off1 + 9216);
                    const int n0 = npp << 2;
                    // term 1 (ph * vh)
#pragma unroll
                    for (int mt = 0; mt < 2; mt++) {
                        mma_bf16(o[mt][n0],     ah[mt], v0h);
                        mma_bf16(o[mt][n0 + 1], ah[mt], v0h + 2);
                        mma_bf16(o[mt][n0 + 2], ah[mt], v1h);
                        mma_bf16(o[mt][n0 + 3], ah[mt], v1h + 2);
                    }
                    // term 2 (ph * vl)
#pragma unroll
                    for (int mt = 0; mt < 2; mt++) {
                        mma_bf16(o[mt][n0],     ah[mt], v0l);
                        mma_bf16(o[mt][n0 + 1], ah[mt], v0l + 2);
                        mma_bf16(o[mt][n0 + 2], ah[mt], v1l);
                        mma_bf16(o[mt][n0 + 3], ah[mt], v1l + 2);
                    }
                    // term 3 (pl * vh)
#pragma unroll
                    for (int mt = 0; mt < 2; mt++) {
                        mma_bf16(o[mt][n0],     al[mt], v0h);
                        mma_bf16(o[mt][n0 + 1], al[mt], v0h + 2);
                        mma_bf16(o[mt][n0 + 2], al[mt], v1h);
                        mma_bf16(o[mt][n0 + 3], al[mt], v1h + 2);
                    }
                }
            }
        }
        __syncthreads();
    }

    // epilogue: normalize + split-write ctx hi/lo
#pragma unroll
    for (int mt = 0; mt < 2; mt++) {
        float inv0 = 1.f / l[mt][0], inv1 = 1.f / l[mt][1];
        int r0 = (w << 5) + (mt << 4) + g, r1 = r0 + 8;
        size_t o0 = (size_t)(b * S_ + q0 + r0) * D_ + h * 64;
        size_t o1 = (size_t)(b * S_ + q0 + r1) * D_ + h * 64;
#pragma unroll
        for (int nt = 0; nt < 8; nt++) {
            int c0 = (nt << 3) + 2 * t;
            unsigned hh, ll;
            split2(o[mt][nt][0] * inv0, o[mt][nt][1] * inv0, hh, ll);
            *(unsigned*)&ctxh[o0 + c0] = hh;
            *(unsigned*)&ctxl[o0 + c0] = ll;
            split2(o[mt][nt][2] * inv1, o[mt][nt][3] * inv1, hh, ll);
            *(unsigned*)&ctxh[o1 + c0] = hh;
            *(unsigned*)&ctxl[o1 + c0] = ll;
        }
    }
}

// ---------------------------------------------------------------------------
// Launch
// ---------------------------------------------------------------------------
extern "C" void kernel_launch(void* const* d_in, const int* in_sizes, int n_in,
                              void* d_out, int out_size)
{
    const float* x      = (const float*)d_in[0];
    // d_in[1] = mask: exactly causal -> applied analytically
    const float* past   = (const float*)d_in[2];
    const float* w_attn = (const float*)d_in[3];
    const float* b_attn = (const float*)d_in[4];
    const float* w_proj = (const float*)d_in[5];
    const float* b_proj = (const float*)d_in[6];

    float* out     = (float*)d_out;
    float* present = out + OUT_OFF;

    void* p;
    float* qkv;
    __nv_bfloat16 *xh, *xl, *ch, *cl, *kvh, *kvl, *wah, *wal, *wph, *wpl;
    cudaGetSymbolAddress(&p, g_qkv); qkv = (float*)p;
    cudaGetSymbolAddress(&p, g_xh);  xh  = (__nv_bfloat16*)p;
    cudaGetSymbolAddress(&p, g_xl);  xl  = (__nv_bfloat16*)p;
    cudaGetSymbolAddress(&p, g_ch);  ch  = (__nv_bfloat16*)p;
    cudaGetSymbolAddress(&p, g_cl);  cl  = (__nv_bfloat16*)p;
    cudaGetSymbolAddress(&p, g_kvh); kvh = (__nv_bfloat16*)p;
    cudaGetSymbolAddress(&p, g_kvl); kvl = (__nv_bfloat16*)p;
    cudaGetSymbolAddress(&p, g_wah); wah = (__nv_bfloat16*)p;
    cudaGetSymbolAddress(&p, g_wal); wal = (__nv_bfloat16*)p;
    cudaGetSymbolAddress(&p, g_wph); wph = (__nv_bfloat16*)p;
    cudaGetSymbolAddress(&p, g_wpl); wpl = (__nv_bfloat16*)p;

    const int GEMM_SMEM  = 2 * 40960;          // 81920
    const int FLASH_SMEM = 2 * 36864 + 36864;  // 110592
    cudaFuncSetAttribute(gemm_presplit,
                         cudaFuncAttributeMaxDynamicSharedMemorySize, GEMM_SMEM);
    cudaFuncSetAttribute(flash_m32,
                         cudaFuncAttributeMaxDynamicSharedMemorySize, FLASH_SMEM);

    // 0. pre-split inputs/weights
    split_x<<<(B_ * S_ * D_ / 4) / 256, 256>>>((const float4*)x, xh, xl);
    split_w<<<dim3(D_ / 32, D3_ / 32), 256>>>(w_attn, wah, wal, D_, D3_);
    split_w<<<dim3(D_ / 32, D_  / 32), 256>>>(w_proj, wph, wpl, D_, D_);

    // 1. QKV projection
    gemm_presplit<<<dim3(D3_ / 128, (B_ * S_) / 128), 256, GEMM_SMEM>>>(
        xh, xl, wah, wal, b_attn, qkv, B_ * S_, D3_, D_);

    // 2. present (f32, into d_out) + K/V hi/lo split
    build_present<<<(B_ * 2 * H_ * T_ * 16) / 256, 256>>>(
        (const float4*)past, (const float4*)qkv, (float4*)present, kvh, kvl);

    // 3. flash attention -> ctx hi/lo
    flash_m32<<<dim3(S_ / 128, B_ * H_), 128, FLASH_SMEM>>>(
        qkv, kvh, kvl, ch, cl);

    // 4. output projection
    gemm_presplit<<<dim3(D_ / 128, (B_ * S_) / 128), 256, GEMM_SMEM>>>(
        ch, cl, wph, wpl, b_proj, out, B_ * S_, D_, D_);
}